// round 14
// baseline (speedup 1.0000x reference)
#include <cuda_runtime.h>
#include <math.h>

#define BATCH 2
#define SEQ   4096
#define EMB   512
#define DQ    64
#define NC    129
#define ZCONST 3967.0f

typedef unsigned long long ull;

// ---- scratch (allocation-free: device globals) ----
__device__ float g_Q[BATCH * SEQ * DQ];
__device__ float g_K[BATCH * SEQ * DQ];
__device__ float g_Vc[BATCH * NC * DQ];
__device__ float g_part[BATCH * 64 * EMB];
__device__ float g_vtp[BATCH * 8 * DQ];
__device__ float4 g_Wp2[256 * DQ];   // [kp][d]: {wq2kp, wq2kp+1, wk2kp, wk2kp+1}

__device__ __forceinline__ void ffma2(ull& acc, ull a, ull b) {
    asm("fma.rn.f32x2 %0, %1, %2, %0;" : "+l"(acc) : "l"(a), "l"(b));
}
__device__ __forceinline__ ull pack2(float lo, float hi) {
    return ((ull)__float_as_uint(hi) << 32) | (ull)__float_as_uint(lo);
}
__device__ __forceinline__ float lo32(ull v) { return __uint_as_float((unsigned)v); }
__device__ __forceinline__ float hi32(ull v) { return __uint_as_float((unsigned)(v >> 32)); }

// ============================================================
// Kernel 0: pack W (kp-major, d contiguous). 128 blocks x 128 thr.
// ============================================================
__global__ void __launch_bounds__(128)
pack_w_kernel(const float* __restrict__ Wq, const float* __restrict__ Wk) {
    const int kp = blockIdx.x * 2 + (threadIdx.x >> 6);
    const int d  = threadIdx.x & 63;
    float4 w;
    w.x = Wq[(size_t)(2 * kp)     * DQ + d];
    w.y = Wq[(size_t)(2 * kp + 1) * DQ + d];
    w.z = Wk[(size_t)(2 * kp)     * DQ + d];
    w.w = Wk[(size_t)(2 * kp + 1) * DQ + d];
    g_Wp2[kp * DQ + d] = w;
}

// ============================================================
// Kernel 1 (mega): 642 blocks x 256 threads.
//  [0,256):   Q/K projection (R7 config), b = bid>>7, n0 = (bid&127)*32
//  [256,384): xsum partials over rows 129..4095 (float2 per thread)
//  [384,642): V projection rows 0..128
// ============================================================
__global__ void __launch_bounds__(256, 3)
mega_kernel(const float* __restrict__ x,
            const float* __restrict__ bq, const float* __restrict__ bk,
            const float* __restrict__ Wv, const float* __restrict__ bv) {
    __shared__ ull xs2[32][64];            // proj x tile (16 KB)
    __shared__ float xsh[EMB];             // vhead row (2 KB)
    __shared__ float red4[4][DQ];          // vhead partials (1 KB)

    const int bid = blockIdx.x, t = threadIdx.x;

    if (bid < 256) {
        // ---------------- Q/K projection ----------------
        const int b  = bid >> 7;
        const int n0 = (bid & 127) * 32;
        const int rg = t & 7;
        const int dg = t >> 3;

        ull qa[4][2], ka[4][2];
#pragma unroll
        for (int i = 0; i < 4; i++)
#pragma unroll
            for (int j = 0; j < 2; j++) { qa[i][j] = 0ull; ka[i][j] = 0ull; }

        const float* xb = x + ((size_t)b * SEQ + n0) * EMB;

        for (int k0 = 0; k0 < EMB; k0 += 128) {
            __syncthreads();
            for (int idx = t; idx < 32 * 32; idx += 256) {
                int r = idx >> 5, c = idx & 31;
                float4 v = *(const float4*)(xb + (size_t)r * EMB + k0 + c * 4);
                int sw = r >> 2;
                xs2[r][(2 * c) ^ sw]     = pack2(v.x, v.y);
                xs2[r][(2 * c + 1) ^ sw] = pack2(v.z, v.w);
            }
            __syncthreads();

            const int kpb = k0 >> 1;
#pragma unroll 4
            for (int kp = 0; kp < 64; kp++) {
                const ulonglong2* wrow =
                    (const ulonglong2*)(g_Wp2 + (size_t)(kpb + kp) * DQ) + dg * 2;
                ulonglong2 w0 = wrow[0];
                ulonglong2 w1 = wrow[1];
                ull x2[4];
#pragma unroll
                for (int i = 0; i < 4; i++)
                    x2[i] = xs2[rg * 4 + i][kp ^ rg];
#pragma unroll
                for (int i = 0; i < 4; i++) {
                    ffma2(qa[i][0], x2[i], w0.x);
                    ffma2(ka[i][0], x2[i], w0.y);
                    ffma2(qa[i][1], x2[i], w1.x);
                    ffma2(ka[i][1], x2[i], w1.y);
                }
            }
        }

#pragma unroll
        for (int j = 0; j < 2; j++) {
            int d = dg * 2 + j;
            float bqv = bq[d], bkv = bk[d];
#pragma unroll
            for (int i = 0; i < 4; i++) {
                int n = n0 + rg * 4 + i;
                g_Q[((size_t)b * SEQ + n) * DQ + d] = lo32(qa[i][j]) + hi32(qa[i][j]) + bqv;
                g_K[((size_t)b * SEQ + n) * DQ + d] = lo32(ka[i][j]) + hi32(ka[i][j]) + bkv;
            }
        }
    } else if (bid < 384) {
        // ---------------- xsum partials ----------------
        const int i = bid - 256;
        const int b = i >> 6, ci = i & 63;
        int r0 = 129 + ci * 62;
        int r1 = r0 + 62; if (r1 > SEQ) r1 = SEQ;
        const float* xb = x + (size_t)b * SEQ * EMB;
        float2 s = make_float2(0.f, 0.f);
#pragma unroll 4
        for (int r = r0; r < r1; r++) {
            float2 v = *(const float2*)(xb + (size_t)r * EMB + t * 2);
            s.x += v.x; s.y += v.y;
        }
        *(float2*)(g_part + (b * 64 + ci) * EMB + t * 2) = s;
    } else {
        // ---------------- V head projection ----------------
        const int i = bid - 384;            // 0..257
        const int b = i / NC, r = i % NC;
        const float* xr = x + ((size_t)b * SEQ + r) * EMB;
        if (t < 128) ((float4*)xsh)[t] = ((const float4*)xr)[t];
        __syncthreads();
        const int d = t & 63, h = t >> 6;   // h = 0..3
        float acc = 0.f;
        const int kb = h * 128;
#pragma unroll 8
        for (int k = 0; k < 128; k++)
            acc = fmaf(xsh[kb + k], Wv[(size_t)(kb + k) * DQ + d], acc);
        red4[h][d] = acc;
        __syncthreads();
        if (t < DQ)
            g_Vc[(b * NC + r) * DQ + t] =
                red4[0][t] + red4[1][t] + red4[2][t] + red4[3][t] + bv[t];
    }
}

// ============================================================
// Kernel 2: vtail partials per k-group: grid (8, 2), 256 threads.
// ============================================================
__global__ void vtail_combine_kernel(const float* __restrict__ Wv) {
    const int kg = blockIdx.x, b = blockIdx.y, t = threadIdx.x;
    __shared__ float red[4][DQ];
    __shared__ float xsum64[DQ];
    __shared__ float p2[4][DQ];
    {
        const int kk = t & 63, g = t >> 6;
        float s = 0.f;
#pragma unroll
        for (int ci = g; ci < 64; ci += 4)
            s += g_part[(b * 64 + ci) * EMB + kg * 64 + kk];
        red[g][kk] = s;
    }
    __syncthreads();
    if (t < DQ) xsum64[t] = red[0][t] + red[1][t] + red[2][t] + red[3][t];
    __syncthreads();
    {
        const int d = t & 63, g2 = t >> 6;
        float acc = 0.f;
#pragma unroll
        for (int kk = g2 * 16; kk < g2 * 16 + 16; kk++)
            acc = fmaf(xsum64[kk], Wv[(size_t)(kg * 64 + kk) * DQ + d], acc);
        p2[g2][d] = acc;
    }
    __syncthreads();
    if (t < DQ)
        g_vtp[(b * 8 + kg) * DQ + t] = p2[0][t] + p2[1][t] + p2[2][t] + p2[3][t];
}

// ============================================================
// Kernel 3: attention core — exact R10 config (best measured: 20.8us).
//  32-row tiles, 256 thr, FFMA2, pitches 66/130, Es overlays Ks.
// ============================================================
#define KROWS 160
#define AP    66
#define EP    130
#define AKS   0
#define AQS   10560
#define AVS   12672
#define AZI   20992
#define AVT   21024
#define A_FLOATS 21088
#define A_BYTES (A_FLOATS * 4)

__global__ void __launch_bounds__(256, 2)
attn_kernel(float* __restrict__ out, const float* __restrict__ bv) {
    extern __shared__ float sm[];
    float* Ks  = sm + AKS;
    float* Es  = sm + AKS;      // overlay after phase 1
    float* Qs  = sm + AQS;
    float* Vst = sm + AVS;      // transposed V: Vst[d][c]
    float* Zi  = sm + AZI;
    float* Vt  = sm + AVT;

    const int b = blockIdx.y, n0 = blockIdx.x * 32, t = threadIdx.x;

    const float* Kb = g_K + (size_t)b * SEQ * DQ;
    for (int idx = t; idx < KROWS * 16; idx += 256) {
        int r = idx >> 4, c4 = idx & 15;
        int j = n0 - 64 + r;
        float4 v = (j >= 0 && j < SEQ) ? *(const float4*)(Kb + (size_t)j * DQ + c4 * 4)
                                       : make_float4(0.f, 0.f, 0.f, 0.f);
        float* p = Ks + r * AP + c4 * 4;
        p[0] = v.x; p[1] = v.y; p[2] = v.z; p[3] = v.w;
    }
    const float* Qb = g_Q + ((size_t)b * SEQ + n0) * DQ;
    for (int idx = t; idx < 32 * 16; idx += 256) {
        int r = idx >> 4, c4 = idx & 15;
        float4 v = *(const float4*)(Qb + (size_t)r * DQ + c4 * 4);
        float* p = Qs + r * AP + c4 * 4;
        p[0] = v.x; p[1] = v.y; p[2] = v.z; p[3] = v.w;
    }
    for (int idx = t; idx < NC * 16; idx += 256) {
        int r = idx >> 4, c4 = idx & 15;
        float4 v = *(const float4*)(g_Vc + ((size_t)b * NC + r) * DQ + c4 * 4);
        Vst[(c4 * 4 + 0) * EP + r] = v.x;
        Vst[(c4 * 4 + 1) * EP + r] = v.y;
        Vst[(c4 * 4 + 2) * EP + r] = v.z;
        Vst[(c4 * 4 + 3) * EP + r] = v.w;
    }
    if (t < DQ) {
        Vst[t * EP + 129] = 0.f;
        float s = ZCONST * bv[t];
#pragma unroll
        for (int kg = 0; kg < 8; kg++) s += g_vtp[(b * 8 + kg) * DQ + t];
        Vt[t] = s;
    }
    __syncthreads();

    const int tx = t & 31, ty = t >> 5;

    ull acc2[4][5];
#pragma unroll
    for (int i = 0; i < 4; i++)
#pragma unroll
        for (int jj = 0; jj < 5; jj++) acc2[i][jj] = 0ull;

#pragma unroll 8
    for (int kp = 0; kp < 32; kp++) {
        ull qv[4], kv[5];
#pragma unroll
        for (int i = 0; i < 4; i++)
            qv[i] = *(const ull*)(Qs + (ty * 4 + i) * AP + kp * 2);
#pragma unroll
        for (int jj = 0; jj < 5; jj++)
            kv[jj] = *(const ull*)(Ks + (tx + 32 * jj) * AP + kp * 2);
#pragma unroll
        for (int i = 0; i < 4; i++)
#pragma unroll
            for (int jj = 0; jj < 5; jj++)
                ffma2(acc2[i][jj], qv[i], kv[jj]);
    }
    __syncthreads();

#pragma unroll
    for (int i = 0; i < 4; i++) {
        int np = ty * 4 + i;
#pragma unroll
        for (int jj = 0; jj < 5; jj++) {
            int cc = tx + 32 * jj;
            int c = cc - np;
            if (c >= 0 && c < NC)
                Es[np * EP + c] = expf(lo32(acc2[i][jj]) + hi32(acc2[i][jj]));
        }
    }
    if (t < 32) Es[t * EP + 129] = 0.f;
    __syncthreads();

    {
        const int w = ty, lane = tx;
#pragma unroll
        for (int rr = 0; rr < 4; rr++) {
            int r = w * 4 + rr;
            float s = Es[r * EP + lane] + Es[r * EP + lane + 32]
                    + Es[r * EP + lane + 64] + Es[r * EP + lane + 96];
            if (lane == 0) s += Es[r * EP + 128];
#pragma unroll
            for (int o = 16; o > 0; o >>= 1) s += __shfl_xor_sync(0xffffffffu, s, o);
            if (lane == 0) Zi[r] = 1.0f / (s + ZCONST);
        }
    }
    __syncthreads();

    ull oacc2[4][2];
#pragma unroll
    for (int i = 0; i < 4; i++) { oacc2[i][0] = 0ull; oacc2[i][1] = 0ull; }

#pragma unroll 5
    for (int kp = 0; kp < 65; kp++) {
        ull ev[4], vv[2];
#pragma unroll
        for (int i = 0; i < 4; i++)
            ev[i] = *(const ull*)(Es + (ty * 4 + i) * EP + kp * 2);
        vv[0] = *(const ull*)(Vst + tx * EP + kp * 2);
        vv[1] = *(const ull*)(Vst + (tx + 32) * EP + kp * 2);
#pragma unroll
        for (int i = 0; i < 4; i++) {
            ffma2(oacc2[i][0], ev[i], vv[0]);
            ffma2(oacc2[i][1], ev[i], vv[1]);
        }
    }

#pragma unroll
    for (int i = 0; i < 4; i++) {
        int np = ty * 4 + i;
        float zi = Zi[np];
        int d0 = tx, d1 = tx + 32;
        out[((size_t)b * SEQ + n0 + np) * DQ + d0] =
            (lo32(oacc2[i][0]) + hi32(oacc2[i][0]) + Vt[d0]) * zi;
        out[((size_t)b * SEQ + n0 + np) * DQ + d1] =
            (lo32(oacc2[i][1]) + hi32(oacc2[i][1]) + Vt[d1]) * zi;
    }
}

// ============================================================
// launcher
// ============================================================
extern "C" void kernel_launch(void* const* d_in, const int* in_sizes, int n_in,
                              void* d_out, int out_size) {
    const float* x  = (const float*)d_in[0];
    const float* Wq = (const float*)d_in[1];
    const float* bq = (const float*)d_in[2];
    const float* Wk = (const float*)d_in[3];
    const float* bk = (const float*)d_in[4];
    const float* Wv = (const float*)d_in[5];
    const float* bv = (const float*)d_in[6];
    float* out = (float*)d_out;

    cudaFuncSetAttribute(attn_kernel, cudaFuncAttributeMaxDynamicSharedMemorySize, A_BYTES);

    pack_w_kernel<<<128, 128>>>(Wq, Wk);
    mega_kernel<<<642, 256>>>(x, bq, bk, Wv, bv);
    vtail_combine_kernel<<<dim3(8, BATCH), 256>>>(Wv);
    attn_kernel<<<dim3(SEQ / 32, BATCH), 256, A_BYTES>>>(out, bv);
}

// round 15
// speedup vs baseline: 1.8408x; 1.8408x over previous
#include <cuda_runtime.h>
#include <math.h>

#define BATCH 2
#define SEQ   4096
#define EMB   512
#define DQ    64
#define NC    129
#define ZCONST 3967.0f

typedef unsigned long long ull;

// ---- scratch (allocation-free: device globals) ----
__device__ float g_Q[BATCH * SEQ * DQ];
__device__ float g_K[BATCH * SEQ * DQ];
__device__ float g_Vc[BATCH * NC * DQ];
__device__ float g_part[BATCH * 64 * EMB];
__device__ float g_vtp[BATCH * 8 * DQ];
__device__ float4 g_Wp2[256 * DQ];   // [kp][d]: {wq2kp, wq2kp+1, wk2kp, wk2kp+1}

__device__ __forceinline__ void ffma2(ull& acc, ull a, ull b) {
    asm("fma.rn.f32x2 %0, %1, %2, %0;" : "+l"(acc) : "l"(a), "l"(b));
}
__device__ __forceinline__ ull pack2(float lo, float hi) {
    return ((ull)__float_as_uint(hi) << 32) | (ull)__float_as_uint(lo);
}
__device__ __forceinline__ float lo32(ull v) { return __uint_as_float((unsigned)v); }
__device__ __forceinline__ float hi32(ull v) { return __uint_as_float((unsigned)(v >> 32)); }

// ============================================================
// Kernel A (prep): 514 blocks x 128 threads.  (exact R10)
// ============================================================
__global__ void __launch_bounds__(128)
prep_kernel(const float* __restrict__ x,
            const float* __restrict__ Wq, const float* __restrict__ Wk,
            const float* __restrict__ Wv, const float* __restrict__ bv) {
    const int bid = blockIdx.x, t = threadIdx.x;

    if (bid < 128) {
        const int kp = bid * 2 + (t >> 6);
        const int d  = t & 63;
        float4 w;
        w.x = Wq[(size_t)(2 * kp)     * DQ + d];
        w.y = Wq[(size_t)(2 * kp + 1) * DQ + d];
        w.z = Wk[(size_t)(2 * kp)     * DQ + d];
        w.w = Wk[(size_t)(2 * kp + 1) * DQ + d];
        g_Wp2[kp * DQ + d] = w;
    } else if (bid < 256) {
        const int i = bid - 128;
        const int b = i >> 6, ci = i & 63;
        int r0 = 129 + ci * 62;
        int r1 = r0 + 62; if (r1 > SEQ) r1 = SEQ;
        const float* xb = x + (size_t)b * SEQ * EMB;
        float4 s = make_float4(0.f, 0.f, 0.f, 0.f);
#pragma unroll 4
        for (int r = r0; r < r1; r++) {
            float4 v = *(const float4*)(xb + (size_t)r * EMB + t * 4);
            s.x += v.x; s.y += v.y; s.z += v.z; s.w += v.w;
        }
        *(float4*)(g_part + (b * 64 + ci) * EMB + t * 4) = s;
    } else {
        const int i = bid - 256;
        const int b = i / NC, r = i % NC;
        __shared__ float xsh[EMB];
        __shared__ float red[2][DQ];
        const float* xr = x + ((size_t)b * SEQ + r) * EMB;
        ((float4*)xsh)[t] = ((const float4*)xr)[t];
        __syncthreads();
        const int d = t & 63, h = t >> 6;
        float acc = 0.f;
        const int kb = h * 256;
#pragma unroll 8
        for (int k = 0; k < 256; k++)
            acc = fmaf(xsh[kb + k], Wv[(size_t)(kb + k) * DQ + d], acc);
        red[h][d] = acc;
        __syncthreads();
        if (t < DQ)
            g_Vc[(b * NC + r) * DQ + t] = red[0][t] + red[1][t] + bv[t];
    }
}

// ============================================================
// Kernel B: vtail partials per k-group: grid (8, 2), 256 threads. (exact R10)
// ============================================================
__global__ void vtail_combine_kernel(const float* __restrict__ Wv) {
    const int kg = blockIdx.x, b = blockIdx.y, t = threadIdx.x;
    __shared__ float red[4][DQ];
    __shared__ float xsum64[DQ];
    __shared__ float p2[4][DQ];
    {
        const int kk = t & 63, g = t >> 6;
        float s = 0.f;
#pragma unroll
        for (int ci = g; ci < 64; ci += 4)
            s += g_part[(b * 64 + ci) * EMB + kg * 64 + kk];
        red[g][kk] = s;
    }
    __syncthreads();
    if (t < DQ) xsum64[t] = red[0][t] + red[1][t] + red[2][t] + red[3][t];
    __syncthreads();
    {
        const int d = t & 63, g2 = t >> 6;
        float acc = 0.f;
#pragma unroll
        for (int kk = g2 * 16; kk < g2 * 16 + 16; kk++)
            acc = fmaf(xsum64[kk], Wv[(size_t)(kg * 64 + kk) * DQ + d], acc);
        p2[g2][d] = acc;
    }
    __syncthreads();
    if (t < DQ)
        g_vtp[(b * 8 + kg) * DQ + t] = p2[0][t] + p2[1][t] + p2[2][t] + p2[3][t];
}

// ============================================================
// Kernel C: Q/K projection (exact R7/R10 config).
// ============================================================
__global__ void __launch_bounds__(256, 3)
proj_qk_kernel(const float* __restrict__ x,
               const float* __restrict__ bq, const float* __restrict__ bk) {
    __shared__ ull xs2[32][64];
    const int b  = blockIdx.y;
    const int n0 = blockIdx.x * 32;
    const int t  = threadIdx.x;
    const int rg = t & 7;
    const int dg = t >> 3;

    ull qa[4][2], ka[4][2];
#pragma unroll
    for (int i = 0; i < 4; i++)
#pragma unroll
        for (int j = 0; j < 2; j++) { qa[i][j] = 0ull; ka[i][j] = 0ull; }

    const float* xb = x + ((size_t)b * SEQ + n0) * EMB;

    for (int k0 = 0; k0 < EMB; k0 += 128) {
        __syncthreads();
        for (int idx = t; idx < 32 * 32; idx += 256) {
            int r = idx >> 5, c = idx & 31;
            float4 v = *(const float4*)(xb + (size_t)r * EMB + k0 + c * 4);
            int sw = r >> 2;
            xs2[r][(2 * c) ^ sw]     = pack2(v.x, v.y);
            xs2[r][(2 * c + 1) ^ sw] = pack2(v.z, v.w);
        }
        __syncthreads();

        const int kpb = k0 >> 1;
#pragma unroll 4
        for (int kp = 0; kp < 64; kp++) {
            const ulonglong2* wrow =
                (const ulonglong2*)(g_Wp2 + (size_t)(kpb + kp) * DQ) + dg * 2;
            ulonglong2 w0 = wrow[0];
            ulonglong2 w1 = wrow[1];
            ull x2[4];
#pragma unroll
            for (int i = 0; i < 4; i++)
                x2[i] = xs2[rg * 4 + i][kp ^ rg];
#pragma unroll
            for (int i = 0; i < 4; i++) {
                ffma2(qa[i][0], x2[i], w0.x);
                ffma2(ka[i][0], x2[i], w0.y);
                ffma2(qa[i][1], x2[i], w1.x);
                ffma2(ka[i][1], x2[i], w1.y);
            }
        }
    }

#pragma unroll
    for (int j = 0; j < 2; j++) {
        int d = dg * 2 + j;
        float bqv = bq[d], bkv = bk[d];
#pragma unroll
        for (int i = 0; i < 4; i++) {
            int n = n0 + rg * 4 + i;
            g_Q[((size_t)b * SEQ + n) * DQ + d] = lo32(qa[i][j]) + hi32(qa[i][j]) + bqv;
            g_K[((size_t)b * SEQ + n) * DQ + d] = lo32(ka[i][j]) + hi32(ka[i][j]) + bkv;
        }
    }
}

// ============================================================
// Kernel D: attention core — R10 config + register double-buffering.
// ============================================================
#define KROWS 160
#define AP    66
#define EP    130
#define AKS   0
#define AQS   10560
#define AVS   12672
#define AZI   20992
#define AVT   21024
#define A_FLOATS 21088
#define A_BYTES (A_FLOATS * 4)

__global__ void __launch_bounds__(256, 2)
attn_kernel(float* __restrict__ out, const float* __restrict__ bv) {
    extern __shared__ float sm[];
    float* Ks  = sm + AKS;
    float* Es  = sm + AKS;      // overlay after phase 1
    float* Qs  = sm + AQS;
    float* Vst = sm + AVS;      // transposed V: Vst[d][c]
    float* Zi  = sm + AZI;
    float* Vt  = sm + AVT;

    const int b = blockIdx.y, n0 = blockIdx.x * 32, t = threadIdx.x;

    const float* Kb = g_K + (size_t)b * SEQ * DQ;
    for (int idx = t; idx < KROWS * 16; idx += 256) {
        int r = idx >> 4, c4 = idx & 15;
        int j = n0 - 64 + r;
        float4 v = (j >= 0 && j < SEQ) ? *(const float4*)(Kb + (size_t)j * DQ + c4 * 4)
                                       : make_float4(0.f, 0.f, 0.f, 0.f);
        float* p = Ks + r * AP + c4 * 4;
        p[0] = v.x; p[1] = v.y; p[2] = v.z; p[3] = v.w;
    }
    const float* Qb = g_Q + ((size_t)b * SEQ + n0) * DQ;
    for (int idx = t; idx < 32 * 16; idx += 256) {
        int r = idx >> 4, c4 = idx & 15;
        float4 v = *(const float4*)(Qb + (size_t)r * DQ + c4 * 4);
        float* p = Qs + r * AP + c4 * 4;
        p[0] = v.x; p[1] = v.y; p[2] = v.z; p[3] = v.w;
    }
    for (int idx = t; idx < NC * 16; idx += 256) {
        int r = idx >> 4, c4 = idx & 15;
        float4 v = *(const float4*)(g_Vc + ((size_t)b * NC + r) * DQ + c4 * 4);
        Vst[(c4 * 4 + 0) * EP + r] = v.x;
        Vst[(c4 * 4 + 1) * EP + r] = v.y;
        Vst[(c4 * 4 + 2) * EP + r] = v.z;
        Vst[(c4 * 4 + 3) * EP + r] = v.w;
    }
    if (t < DQ) {
        Vst[t * EP + 129] = 0.f;
        float s = ZCONST * bv[t];
#pragma unroll
        for (int kg = 0; kg < 8; kg++) s += g_vtp[(b * 8 + kg) * DQ + t];
        Vt[t] = s;
    }
    __syncthreads();

    const int tx = t & 31, ty = t >> 5;

    // --- phase 1: double-buffered FFMA2 over k-pairs ---
    ull acc2[4][5];
#pragma unroll
    for (int i = 0; i < 4; i++)
#pragma unroll
        for (int jj = 0; jj < 5; jj++) acc2[i][jj] = 0ull;

    ull qv[2][4], kv[2][5];
#pragma unroll
    for (int i = 0; i < 4; i++)
        qv[0][i] = *(const ull*)(Qs + (ty * 4 + i) * AP);
#pragma unroll
    for (int jj = 0; jj < 5; jj++)
        kv[0][jj] = *(const ull*)(Ks + (tx + 32 * jj) * AP);

#pragma unroll
    for (int kp = 0; kp < 32; kp++) {
        const int cur = kp & 1, nxt = cur ^ 1;
        if (kp < 31) {
#pragma unroll
            for (int i = 0; i < 4; i++)
                qv[nxt][i] = *(const ull*)(Qs + (ty * 4 + i) * AP + (kp + 1) * 2);
#pragma unroll
            for (int jj = 0; jj < 5; jj++)
                kv[nxt][jj] = *(const ull*)(Ks + (tx + 32 * jj) * AP + (kp + 1) * 2);
        }
#pragma unroll
        for (int i = 0; i < 4; i++)
#pragma unroll
            for (int jj = 0; jj < 5; jj++)
                ffma2(acc2[i][jj], qv[cur][i], kv[cur][jj]);
    }
    __syncthreads();

#pragma unroll
    for (int i = 0; i < 4; i++) {
        int np = ty * 4 + i;
#pragma unroll
        for (int jj = 0; jj < 5; jj++) {
            int cc = tx + 32 * jj;
            int c = cc - np;
            if (c >= 0 && c < NC)
                Es[np * EP + c] = expf(lo32(acc2[i][jj]) + hi32(acc2[i][jj]));
        }
    }
    if (t < 32) Es[t * EP + 129] = 0.f;
    __syncthreads();

    {
        const int w = ty, lane = tx;
#pragma unroll
        for (int rr = 0; rr < 4; rr++) {
            int r = w * 4 + rr;
            float s = Es[r * EP + lane] + Es[r * EP + lane + 32]
                    + Es[r * EP + lane + 64] + Es[r * EP + lane + 96];
            if (lane == 0) s += Es[r * EP + 128];
#pragma unroll
            for (int o = 16; o > 0; o >>= 1) s += __shfl_xor_sync(0xffffffffu, s, o);
            if (lane == 0) Zi[r] = 1.0f / (s + ZCONST);
        }
    }
    __syncthreads();

    // --- phase 2: double-buffered FFMA2 over c-pairs (65) ---
    ull oacc2[4][2];
#pragma unroll
    for (int i = 0; i < 4; i++) { oacc2[i][0] = 0ull; oacc2[i][1] = 0ull; }

    ull ev[2][4], vv[2][2];
#pragma unroll
    for (int i = 0; i < 4; i++)
        ev[0][i] = *(const ull*)(Es + (ty * 4 + i) * EP);
    vv[0][0] = *(const ull*)(Vst + tx * EP);
    vv[0][1] = *(const ull*)(Vst + (tx + 32) * EP);

#pragma unroll 4
    for (int kp = 0; kp < 65; kp++) {
        const int cur = kp & 1, nxt = cur ^ 1;
        if (kp < 64) {
#pragma unroll
            for (int i = 0; i < 4; i++)
                ev[nxt][i] = *(const ull*)(Es + (ty * 4 + i) * EP + (kp + 1) * 2);
            vv[nxt][0] = *(const ull*)(Vst + tx * EP + (kp + 1) * 2);
            vv[nxt][1] = *(const ull*)(Vst + (tx + 32) * EP + (kp + 1) * 2);
        }
#pragma unroll
        for (int i = 0; i < 4; i++) {
            ffma2(oacc2[i][0], ev[cur][i], vv[cur][0]);
            ffma2(oacc2[i][1], ev[cur][i], vv[cur][1]);
        }
    }

#pragma unroll
    for (int i = 0; i < 4; i++) {
        int np = ty * 4 + i;
        float zi = Zi[np];
        int d0 = tx, d1 = tx + 32;
        out[((size_t)b * SEQ + n0 + np) * DQ + d0] =
            (lo32(oacc2[i][0]) + hi32(oacc2[i][0]) + Vt[d0]) * zi;
        out[((size_t)b * SEQ + n0 + np) * DQ + d1] =
            (lo32(oacc2[i][1]) + hi32(oacc2[i][1]) + Vt[d1]) * zi;
    }
}

// ============================================================
// launcher (exact R10 structure)
// ============================================================
extern "C" void kernel_launch(void* const* d_in, const int* in_sizes, int n_in,
                              void* d_out, int out_size) {
    const float* x  = (const float*)d_in[0];
    const float* Wq = (const float*)d_in[1];
    const float* bq = (const float*)d_in[2];
    const float* Wk = (const float*)d_in[3];
    const float* bk = (const float*)d_in[4];
    const float* Wv = (const float*)d_in[5];
    const float* bv = (const float*)d_in[6];
    float* out = (float*)d_out;

    cudaFuncSetAttribute(attn_kernel, cudaFuncAttributeMaxDynamicSharedMemorySize, A_BYTES);

    prep_kernel<<<514, 128>>>(x, Wq, Wk, Wv, bv);
    vtail_combine_kernel<<<dim3(8, BATCH), 256>>>(Wv);
    proj_qk_kernel<<<dim3(SEQ / 32, BATCH), 256>>>(x, bq, bk);
    attn_kernel<<<dim3(SEQ / 32, BATCH), 256, A_BYTES>>>(out, bv);
}